// round 2
// baseline (speedup 1.0000x reference)
#include <cuda_runtime.h>
#include <cstdint>

#define BDIM 8
#define CDIM 256
#define SDIM 16384
#define KSPLIT 16
#define KC (SDIM / KSPLIT)   // 1024
#define BK 32

// Scratch (static device memory — allowed; no runtime allocation).
__device__ float g_Ep[KSPLIT][BDIM * CDIM * CDIM];  // split-K partials of E, 32 MB
__device__ float g_W[BDIM * CDIM * CDIM];           // softmax weights, 2 MB

__device__ __forceinline__ uint32_t tf32u(float x) {
    uint32_t u;
    asm("cvt.rna.tf32.f32 %0, %1;" : "=r"(u) : "f"(x));
    return u;
}

// hi = tf32(v), lo = tf32(v - hi)
__device__ __forceinline__ void split_tf32(float v, uint32_t& hi, uint32_t& lo) {
    hi = tf32u(v);
    lo = tf32u(v - __uint_as_float(hi));
}

__device__ __forceinline__ void mma_tf32(float* d, const uint32_t* a, const uint32_t* b) {
    asm volatile(
        "mma.sync.aligned.m16n8k8.row.col.f32.tf32.tf32.f32 "
        "{%0,%1,%2,%3}, {%4,%5,%6,%7}, {%8,%9}, {%0,%1,%2,%3};\n"
        : "+f"(d[0]), "+f"(d[1]), "+f"(d[2]), "+f"(d[3])
        : "r"(a[0]), "r"(a[1]), "r"(a[2]), "r"(a[3]), "r"(b[0]), "r"(b[1]));
}

// 3xTF32: D += ah*bh + ah*bl + al*bh
__device__ __forceinline__ void mma3(float* d, const uint32_t* ah, const uint32_t* al,
                                     const uint32_t* bh, const uint32_t* bl) {
    mma_tf32(d, ah, bh);
    mma_tf32(d, al, bh);
    mma_tf32(d, ah, bl);
}

// ---------------------------------------------------------------------------
// GEMM1: E_partial[ks] = V[:, ks-chunk] * V[:, ks-chunk]^T  (per batch)
// CTA computes a 128x128 tile of E over a K-chunk of 1024. 3xTF32 precision.
// ---------------------------------------------------------------------------
__global__ __launch_bounds__(256) void gemm1_kernel(const float* __restrict__ x) {
    const int ks   = blockIdx.x;           // 0..KSPLIT-1
    const int tile = blockIdx.y;           // 0..3 (2x2 of 128)
    const int b    = blockIdx.z;
    const int tm = (tile >> 1) * 128;
    const int tn = (tile & 1) * 128;
    const float* __restrict__ V = x + (size_t)b * CDIM * SDIM;
    const int k0 = ks * KC;

    __shared__ float As[128][36];
    __shared__ float Bs[128][36];

    const int tid  = threadIdx.x;
    const int lane = tid & 31;
    const int wid  = tid >> 5;
    const int gid  = lane >> 2;           // 0..7
    const int tig  = lane & 3;            // 0..3
    const int warpM = wid >> 2;           // 0..1  (64 rows each)
    const int warpN = wid & 3;            // 0..3  (32 cols each)

    float acc[4][4][4];
    #pragma unroll
    for (int i = 0; i < 4; i++)
        #pragma unroll
        for (int j = 0; j < 4; j++)
            #pragma unroll
            for (int k = 0; k < 4; k++) acc[i][j][k] = 0.f;

    const int ldRow = tid >> 3;           // 0..31
    const int ldCol = (tid & 7) * 4;      // 0..28

    for (int kb = 0; kb < KC; kb += BK) {
        #pragma unroll
        for (int p = 0; p < 4; p++) {
            const int row = p * 32 + ldRow;
            *(float4*)&As[row][ldCol] = *(const float4*)(V + (size_t)(tm + row) * SDIM + k0 + kb + ldCol);
            *(float4*)&Bs[row][ldCol] = *(const float4*)(V + (size_t)(tn + row) * SDIM + k0 + kb + ldCol);
        }
        __syncthreads();
        #pragma unroll
        for (int kk = 0; kk < BK; kk += 8) {
            uint32_t ah[4][4], al[4][4], bh[4][2], bl[4][2];
            #pragma unroll
            for (int mr = 0; mr < 4; mr++) {
                const int r0 = warpM * 64 + mr * 16;
                split_tf32(As[r0 + gid    ][kk + tig    ], ah[mr][0], al[mr][0]);
                split_tf32(As[r0 + 8 + gid][kk + tig    ], ah[mr][1], al[mr][1]);
                split_tf32(As[r0 + gid    ][kk + tig + 4], ah[mr][2], al[mr][2]);
                split_tf32(As[r0 + 8 + gid][kk + tig + 4], ah[mr][3], al[mr][3]);
            }
            #pragma unroll
            for (int nc = 0; nc < 4; nc++) {
                const int n0 = warpN * 32 + nc * 8;
                split_tf32(Bs[n0 + gid][kk + tig    ], bh[nc][0], bl[nc][0]);
                split_tf32(Bs[n0 + gid][kk + tig + 4], bh[nc][1], bl[nc][1]);
            }
            #pragma unroll
            for (int mr = 0; mr < 4; mr++)
                #pragma unroll
                for (int nc = 0; nc < 4; nc++)
                    mma3(acc[mr][nc], ah[mr], al[mr], bh[nc], bl[nc]);
        }
        __syncthreads();
    }

    float* Ep = &g_Ep[ks][(size_t)b * CDIM * CDIM];
    #pragma unroll
    for (int mr = 0; mr < 4; mr++) {
        const int r = tm + warpM * 64 + mr * 16 + gid;
        #pragma unroll
        for (int nc = 0; nc < 4; nc++) {
            const int c = tn + warpN * 32 + nc * 8 + tig * 2;
            *(float2*)&Ep[(size_t)r * CDIM + c]       = make_float2(acc[mr][nc][0], acc[mr][nc][1]);
            *(float2*)&Ep[(size_t)(r + 8) * CDIM + c] = make_float2(acc[mr][nc][2], acc[mr][nc][3]);
        }
    }
}

// ---------------------------------------------------------------------------
// Softmax: reduce split-K partials, then w[row,:] = softmax(-E[row,:]).
// (max-shift in the reference is softmax-shift-invariant.)
// One block (256 threads) per row; 8*256 = 2048 rows.
// ---------------------------------------------------------------------------
__global__ __launch_bounds__(256) void softmax_kernel() {
    const int row = blockIdx.x;
    const int tid = threadIdx.x;       // == CDIM
    const int lane = tid & 31;
    const int wid  = tid >> 5;

    float e = 0.f;
    #pragma unroll
    for (int ks = 0; ks < KSPLIT; ks++)
        e += g_Ep[ks][(size_t)row * CDIM + tid];

    __shared__ float red[8];

    // row min (=> max of -E)
    float m = e;
    #pragma unroll
    for (int o = 16; o > 0; o >>= 1) m = fminf(m, __shfl_xor_sync(0xffffffffu, m, o));
    if (lane == 0) red[wid] = m;
    __syncthreads();
    float mn = red[0];
    #pragma unroll
    for (int i = 1; i < 8; i++) mn = fminf(mn, red[i]);
    __syncthreads();

    const float ex = expf(mn - e);

    float s = ex;
    #pragma unroll
    for (int o = 16; o > 0; o >>= 1) s += __shfl_xor_sync(0xffffffffu, s, o);
    if (lane == 0) red[wid] = s;
    __syncthreads();
    float st = red[0];
    #pragma unroll
    for (int i = 1; i < 8; i++) st += red[i];

    g_W[(size_t)row * CDIM + tid] = ex / st;
}

// ---------------------------------------------------------------------------
// GEMM2: out = alpha * (W @ V) + x.  CTA: 128 C-rows x 128 S-cols, K=256.
// 3xTF32 precision.
// ---------------------------------------------------------------------------
__global__ __launch_bounds__(256) void gemm2_kernel(const float* __restrict__ x,
                                                    const float* __restrict__ alpha,
                                                    float* __restrict__ out) {
    const int sTile = blockIdx.x;   // 0..127
    const int mTile = blockIdx.y;   // 0..1
    const int b     = blockIdx.z;
    const int s0 = sTile * 128;
    const int m0 = mTile * 128;
    const float* __restrict__ V  = x + (size_t)b * CDIM * SDIM;
    const float* __restrict__ Wm = g_W + (size_t)b * CDIM * CDIM;

    __shared__ float As[128][36];    // W tile [m][k]
    __shared__ float Bs[32][136];    // V tile [k][n]

    const int tid  = threadIdx.x;
    const int lane = tid & 31;
    const int wid  = tid >> 5;
    const int gid  = lane >> 2;
    const int tig  = lane & 3;
    const int warpM = wid >> 2;
    const int warpN = wid & 3;

    float acc[4][4][4];
    #pragma unroll
    for (int i = 0; i < 4; i++)
        #pragma unroll
        for (int j = 0; j < 4; j++)
            #pragma unroll
            for (int k = 0; k < 4; k++) acc[i][j][k] = 0.f;

    const int aRow = tid >> 3;            // 0..31
    const int aCol = (tid & 7) * 4;
    const int bRowBase = tid >> 5;        // 0..7
    const int bCol = (tid & 31) * 4;      // 0..124

    for (int kb = 0; kb < CDIM; kb += BK) {
        #pragma unroll
        for (int p = 0; p < 4; p++) {
            const int row = p * 32 + aRow;
            *(float4*)&As[row][aCol] = *(const float4*)(Wm + (size_t)(m0 + row) * CDIM + kb + aCol);
        }
        #pragma unroll
        for (int p = 0; p < 4; p++) {
            const int kr = p * 8 + bRowBase;
            *(float4*)&Bs[kr][bCol] = *(const float4*)(V + (size_t)(kb + kr) * SDIM + s0 + bCol);
        }
        __syncthreads();
        #pragma unroll
        for (int kk = 0; kk < BK; kk += 8) {
            uint32_t ah[4][4], al[4][4], bh[4][2], bl[4][2];
            #pragma unroll
            for (int mr = 0; mr < 4; mr++) {
                const int r0 = warpM * 64 + mr * 16;
                split_tf32(As[r0 + gid    ][kk + tig    ], ah[mr][0], al[mr][0]);
                split_tf32(As[r0 + 8 + gid][kk + tig    ], ah[mr][1], al[mr][1]);
                split_tf32(As[r0 + gid    ][kk + tig + 4], ah[mr][2], al[mr][2]);
                split_tf32(As[r0 + 8 + gid][kk + tig + 4], ah[mr][3], al[mr][3]);
            }
            #pragma unroll
            for (int nc = 0; nc < 4; nc++) {
                const int n0 = warpN * 32 + nc * 8;
                split_tf32(Bs[kk + tig    ][n0 + gid], bh[nc][0], bl[nc][0]);
                split_tf32(Bs[kk + tig + 4][n0 + gid], bh[nc][1], bl[nc][1]);
            }
            #pragma unroll
            for (int mr = 0; mr < 4; mr++)
                #pragma unroll
                for (int nc = 0; nc < 4; nc++)
                    mma3(acc[mr][nc], ah[mr], al[mr], bh[nc], bl[nc]);
        }
        __syncthreads();
    }

    const float av = *alpha;
    float* outB = out + (size_t)b * CDIM * SDIM;
    #pragma unroll
    for (int mr = 0; mr < 4; mr++) {
        const int r = m0 + warpM * 64 + mr * 16 + gid;
        #pragma unroll
        for (int nc = 0; nc < 4; nc++) {
            const int s = s0 + warpN * 32 + nc * 8 + tig * 2;
            const size_t i0 = (size_t)r * SDIM + s;
            const size_t i1 = i0 + (size_t)8 * SDIM;
            const float2 x0 = *(const float2*)(V + i0);
            const float2 x1 = *(const float2*)(V + i1);
            *(float2*)(outB + i0) = make_float2(fmaf(av, acc[mr][nc][0], x0.x),
                                                fmaf(av, acc[mr][nc][1], x0.y));
            *(float2*)(outB + i1) = make_float2(fmaf(av, acc[mr][nc][2], x1.x),
                                                fmaf(av, acc[mr][nc][3], x1.y));
        }
    }
}

extern "C" void kernel_launch(void* const* d_in, const int* in_sizes, int n_in,
                              void* d_out, int out_size) {
    const float* x     = (const float*)d_in[0];
    const float* alpha = (const float*)d_in[1];
    float* out = (float*)d_out;

    gemm1_kernel<<<dim3(KSPLIT, 4, BDIM), 256>>>(x);
    softmax_kernel<<<BDIM * CDIM, 256>>>();
    gemm2_kernel<<<dim3(SDIM / 128, 2, BDIM), 256>>>(x, alpha, out);
}

// round 3
// speedup vs baseline: 1.4084x; 1.4084x over previous
#include <cuda_runtime.h>
#include <cstdint>

#define BDIM 8
#define CDIM 256
#define SDIM 16384
#define KSPLIT 16
#define KC (SDIM / KSPLIT)   // 1024
#define BK 32

// Scratch (static device memory — allowed; no runtime allocation).
__device__ float g_Ep[KSPLIT][BDIM * CDIM * CDIM];  // split-K partials of E, 32 MB
__device__ float g_W[BDIM * CDIM * CDIM];           // softmax weights, 2 MB

__device__ __forceinline__ uint32_t tf32u(float x) {
    uint32_t u;
    asm("cvt.rna.tf32.f32 %0, %1;" : "=r"(u) : "f"(x));
    return u;
}

__device__ __forceinline__ void split_tf32(float v, uint32_t& hi, uint32_t& lo) {
    hi = tf32u(v);
    lo = tf32u(v - __uint_as_float(hi));
}

__device__ __forceinline__ void mma_tf32(float* d, const uint32_t* a, const uint32_t* b) {
    asm volatile(
        "mma.sync.aligned.m16n8k8.row.col.f32.tf32.tf32.f32 "
        "{%0,%1,%2,%3}, {%4,%5,%6,%7}, {%8,%9}, {%0,%1,%2,%3};\n"
        : "+f"(d[0]), "+f"(d[1]), "+f"(d[2]), "+f"(d[3])
        : "r"(a[0]), "r"(a[1]), "r"(a[2]), "r"(a[3]), "r"(b[0]), "r"(b[1]));
}

__device__ __forceinline__ void mma3(float* d, const uint32_t* ah, const uint32_t* al,
                                     const uint32_t* bh, const uint32_t* bl) {
    mma_tf32(d, ah, bh);
    mma_tf32(d, al, bh);
    mma_tf32(d, ah, bl);
}

__device__ __forceinline__ void cp16(void* s, const void* g) {
    uint32_t sa = (uint32_t)__cvta_generic_to_shared(s);
    asm volatile("cp.async.cg.shared.global [%0], [%1], 16;" :: "r"(sa), "l"(g));
}
#define CP_COMMIT() asm volatile("cp.async.commit_group;")
template <int N> __device__ __forceinline__ void cp_wait() {
    asm volatile("cp.async.wait_group %0;" :: "n"(N));
}

// ---------------------------------------------------------------------------
// GEMM1: E_partial[ks] = V_chunk * V_chunk^T, exploiting symmetry.
// grid.y = 3: tile 0 = (0,0), tile 1 = (128,128), tile 2 = (0,128) + mirror.
// 2-stage cp.async pipeline. 3xTF32.
// ---------------------------------------------------------------------------
__global__ __launch_bounds__(256) void gemm1_kernel(const float* __restrict__ x) {
    const int ks   = blockIdx.x;
    const int tile = blockIdx.y;           // 0..2
    const int b    = blockIdx.z;
    const int tm = (tile == 1) ? 128 : 0;
    const int tn = (tile == 0) ? 0 : 128;
    const bool diag = (tile < 2);
    const float* __restrict__ V = x + (size_t)b * CDIM * SDIM;
    const int k0 = ks * KC;

    extern __shared__ float smem[];
    const int TILE = 128 * 36;             // one operand tile (padded)

    const int tid  = threadIdx.x;
    const int lane = tid & 31;
    const int wid  = tid >> 5;
    const int gid  = lane >> 2;
    const int tig  = lane & 3;
    const int warpM = wid >> 2;            // 0..1
    const int warpN = wid & 3;             // 0..3

    float acc[4][4][4];
    #pragma unroll
    for (int i = 0; i < 4; i++)
        #pragma unroll
        for (int j = 0; j < 4; j++)
            #pragma unroll
            for (int k = 0; k < 4; k++) acc[i][j][k] = 0.f;

    const int ldRow = tid >> 3;            // 0..31
    const int ldCol = (tid & 7) * 4;       // 0..28

    auto issue = [&](int buf, int kb) {
        float* A = smem + buf * 2 * TILE;
        float* B = A + TILE;
        #pragma unroll
        for (int p = 0; p < 4; p++) {
            const int row = p * 32 + ldRow;
            cp16(A + row * 36 + ldCol, V + (size_t)(tm + row) * SDIM + k0 + kb + ldCol);
            if (!diag)
                cp16(B + row * 36 + ldCol, V + (size_t)(tn + row) * SDIM + k0 + kb + ldCol);
        }
        CP_COMMIT();
    };

    issue(0, 0);
    int buf = 0;

    for (int kb = 0; kb < KC; kb += BK) {
        const bool more = (kb + BK < KC);
        if (more) issue(buf ^ 1, kb + BK);
        if (more) cp_wait<1>(); else cp_wait<0>();
        __syncthreads();

        float* A = smem + buf * 2 * TILE;
        float* B = diag ? A : (A + TILE);

        #pragma unroll
        for (int kk = 0; kk < BK; kk += 8) {
            uint32_t ah[4][4], al[4][4], bh[4][2], bl[4][2];
            #pragma unroll
            for (int mr = 0; mr < 4; mr++) {
                const int r0 = warpM * 64 + mr * 16;
                split_tf32(A[(r0 + gid    ) * 36 + kk + tig    ], ah[mr][0], al[mr][0]);
                split_tf32(A[(r0 + 8 + gid) * 36 + kk + tig    ], ah[mr][1], al[mr][1]);
                split_tf32(A[(r0 + gid    ) * 36 + kk + tig + 4], ah[mr][2], al[mr][2]);
                split_tf32(A[(r0 + 8 + gid) * 36 + kk + tig + 4], ah[mr][3], al[mr][3]);
            }
            #pragma unroll
            for (int nc = 0; nc < 4; nc++) {
                const int n0 = warpN * 32 + nc * 8;
                split_tf32(B[(n0 + gid) * 36 + kk + tig    ], bh[nc][0], bl[nc][0]);
                split_tf32(B[(n0 + gid) * 36 + kk + tig + 4], bh[nc][1], bl[nc][1]);
            }
            #pragma unroll
            for (int mr = 0; mr < 4; mr++)
                #pragma unroll
                for (int nc = 0; nc < 4; nc++)
                    mma3(acc[mr][nc], ah[mr], al[mr], bh[nc], bl[nc]);
        }
        __syncthreads();
        buf ^= 1;
    }

    float* Ep = &g_Ep[ks][(size_t)b * CDIM * CDIM];
    #pragma unroll
    for (int mr = 0; mr < 4; mr++) {
        const int r = tm + warpM * 64 + mr * 16 + gid;
        #pragma unroll
        for (int nc = 0; nc < 4; nc++) {
            const int c = tn + warpN * 32 + nc * 8 + tig * 2;
            *(float2*)&Ep[(size_t)r * CDIM + c]       = make_float2(acc[mr][nc][0], acc[mr][nc][1]);
            *(float2*)&Ep[(size_t)(r + 8) * CDIM + c] = make_float2(acc[mr][nc][2], acc[mr][nc][3]);
            if (!diag) {  // mirror into the (128,0) quadrant: E[c][r] = E[r][c]
                Ep[(size_t)c * CDIM + r]           = acc[mr][nc][0];
                Ep[(size_t)(c + 1) * CDIM + r]     = acc[mr][nc][1];
                Ep[(size_t)c * CDIM + r + 8]       = acc[mr][nc][2];
                Ep[(size_t)(c + 1) * CDIM + r + 8] = acc[mr][nc][3];
            }
        }
    }
}

// ---------------------------------------------------------------------------
// Softmax: reduce split-K partials, w[row,:] = softmax(-E[row,:]).
// ---------------------------------------------------------------------------
__global__ __launch_bounds__(256) void softmax_kernel() {
    const int row = blockIdx.x;
    const int tid = threadIdx.x;
    const int lane = tid & 31;
    const int wid  = tid >> 5;

    float e = 0.f;
    #pragma unroll
    for (int ks = 0; ks < KSPLIT; ks++)
        e += g_Ep[ks][(size_t)row * CDIM + tid];

    __shared__ float red[8];

    float m = e;
    #pragma unroll
    for (int o = 16; o > 0; o >>= 1) m = fminf(m, __shfl_xor_sync(0xffffffffu, m, o));
    if (lane == 0) red[wid] = m;
    __syncthreads();
    float mn = red[0];
    #pragma unroll
    for (int i = 1; i < 8; i++) mn = fminf(mn, red[i]);
    __syncthreads();

    const float ex = expf(mn - e);

    float s = ex;
    #pragma unroll
    for (int o = 16; o > 0; o >>= 1) s += __shfl_xor_sync(0xffffffffu, s, o);
    if (lane == 0) red[wid] = s;
    __syncthreads();
    float st = red[0];
    #pragma unroll
    for (int i = 1; i < 8; i++) st += red[i];

    g_W[(size_t)row * CDIM + tid] = ex / st;
}

// ---------------------------------------------------------------------------
// GEMM2: out = alpha * (W @ V) + x.  2-stage cp.async pipeline. 3xTF32.
// ---------------------------------------------------------------------------
__global__ __launch_bounds__(256) void gemm2_kernel(const float* __restrict__ x,
                                                    const float* __restrict__ alpha,
                                                    float* __restrict__ out) {
    const int sTile = blockIdx.x;
    const int mTile = blockIdx.y;
    const int b     = blockIdx.z;
    const int s0 = sTile * 128;
    const int m0 = mTile * 128;
    const float* __restrict__ V  = x + (size_t)b * CDIM * SDIM;
    const float* __restrict__ Wm = g_W + (size_t)b * CDIM * CDIM;

    extern __shared__ float smem[];
    const int ATILE = 128 * 36;   // W tile [m][k]
    const int BTILE = 32 * 136;   // V tile [k][n]
    const int STAGE = ATILE + BTILE;

    const int tid  = threadIdx.x;
    const int lane = tid & 31;
    const int wid  = tid >> 5;
    const int gid  = lane >> 2;
    const int tig  = lane & 3;
    const int warpM = wid >> 2;
    const int warpN = wid & 3;

    float acc[4][4][4];
    #pragma unroll
    for (int i = 0; i < 4; i++)
        #pragma unroll
        for (int j = 0; j < 4; j++)
            #pragma unroll
            for (int k = 0; k < 4; k++) acc[i][j][k] = 0.f;

    const int aRow = tid >> 3;            // 0..31
    const int aCol = (tid & 7) * 4;
    const int bRowBase = tid >> 5;        // 0..7
    const int bCol = (tid & 31) * 4;      // 0..124

    auto issue = [&](int buf, int kb) {
        float* A = smem + buf * STAGE;
        float* B = A + ATILE;
        #pragma unroll
        for (int p = 0; p < 4; p++) {
            const int row = p * 32 + aRow;
            cp16(A + row * 36 + aCol, Wm + (size_t)(m0 + row) * CDIM + kb + aCol);
        }
        #pragma unroll
        for (int p = 0; p < 4; p++) {
            const int kr = p * 8 + bRowBase;
            cp16(B + kr * 136 + bCol, V + (size_t)(kb + kr) * SDIM + s0 + bCol);
        }
        CP_COMMIT();
    };

    issue(0, 0);
    int buf = 0;

    for (int kb = 0; kb < CDIM; kb += BK) {
        const bool more = (kb + BK < CDIM);
        if (more) issue(buf ^ 1, kb + BK);
        if (more) cp_wait<1>(); else cp_wait<0>();
        __syncthreads();

        float* A = smem + buf * STAGE;
        float* B = A + ATILE;

        #pragma unroll
        for (int kk = 0; kk < BK; kk += 8) {
            uint32_t ah[4][4], al[4][4], bh[4][2], bl[4][2];
            #pragma unroll
            for (int mr = 0; mr < 4; mr++) {
                const int r0 = warpM * 64 + mr * 16;
                split_tf32(A[(r0 + gid    ) * 36 + kk + tig    ], ah[mr][0], al[mr][0]);
                split_tf32(A[(r0 + 8 + gid) * 36 + kk + tig    ], ah[mr][1], al[mr][1]);
                split_tf32(A[(r0 + gid    ) * 36 + kk + tig + 4], ah[mr][2], al[mr][2]);
                split_tf32(A[(r0 + 8 + gid) * 36 + kk + tig + 4], ah[mr][3], al[mr][3]);
            }
            #pragma unroll
            for (int nc = 0; nc < 4; nc++) {
                const int n0 = warpN * 32 + nc * 8;
                split_tf32(B[(kk + tig    ) * 136 + n0 + gid], bh[nc][0], bl[nc][0]);
                split_tf32(B[(kk + tig + 4) * 136 + n0 + gid], bh[nc][1], bl[nc][1]);
            }
            #pragma unroll
            for (int mr = 0; mr < 4; mr++)
                #pragma unroll
                for (int nc = 0; nc < 4; nc++)
                    mma3(acc[mr][nc], ah[mr], al[mr], bh[nc], bl[nc]);
        }
        __syncthreads();
        buf ^= 1;
    }

    const float av = *alpha;
    float* outB = out + (size_t)b * CDIM * SDIM;
    #pragma unroll
    for (int mr = 0; mr < 4; mr++) {
        const int r = m0 + warpM * 64 + mr * 16 + gid;
        #pragma unroll
        for (int nc = 0; nc < 4; nc++) {
            const int s = s0 + warpN * 32 + nc * 8 + tig * 2;
            const size_t i0 = (size_t)r * SDIM + s;
            const size_t i1 = i0 + (size_t)8 * SDIM;
            const float2 x0 = *(const float2*)(V + i0);
            const float2 x1 = *(const float2*)(V + i1);
            *(float2*)(outB + i0) = make_float2(fmaf(av, acc[mr][nc][0], x0.x),
                                                fmaf(av, acc[mr][nc][1], x0.y));
            *(float2*)(outB + i1) = make_float2(fmaf(av, acc[mr][nc][2], x1.x),
                                                fmaf(av, acc[mr][nc][3], x1.y));
        }
    }
}

extern "C" void kernel_launch(void* const* d_in, const int* in_sizes, int n_in,
                              void* d_out, int out_size) {
    const float* x     = (const float*)d_in[0];
    const float* alpha = (const float*)d_in[1];
    float* out = (float*)d_out;

    const int smem1 = 4 * 128 * 36 * 4;                    // 73728 B
    const int smem2 = 2 * (128 * 36 + 32 * 136) * 4;       // 71680 B
    cudaFuncSetAttribute(gemm1_kernel, cudaFuncAttributeMaxDynamicSharedMemorySize, smem1);
    cudaFuncSetAttribute(gemm2_kernel, cudaFuncAttributeMaxDynamicSharedMemorySize, smem2);

    gemm1_kernel<<<dim3(KSPLIT, 3, BDIM), 256, smem1>>>(x);
    softmax_kernel<<<BDIM * CDIM, 256>>>();
    gemm2_kernel<<<dim3(SDIM / 128, 2, BDIM), 256, smem2>>>(x, alpha, out);
}

// round 4
// speedup vs baseline: 1.7653x; 1.2534x over previous
#include <cuda_runtime.h>
#include <cstdint>

#define BDIM 8
#define CDIM 256
#define SDIM 16384
#define KSPLIT 16
#define KC (SDIM / KSPLIT)   // 1024
#define BK 32

// Scratch (static device memory — allowed; no runtime allocation).
__device__ float g_Ep[KSPLIT][BDIM * CDIM * CDIM];  // split-K partials of E, 32 MB
__device__ float g_W[BDIM * CDIM * CDIM];           // softmax weights, 2 MB

// Mask-based 3xTF32 split: hi = raw fp32 (tensor core truncates to tf32),
// lo = v - trunc_tf32(v).  No cvt instructions.
__device__ __forceinline__ void split_mask(float v, uint32_t& hi, uint32_t& lo) {
    const uint32_t u = __float_as_uint(v);
    hi = u;
    lo = __float_as_uint(v - __uint_as_float(u & 0xFFFFE000u));
}

__device__ __forceinline__ void mma_tf32(float* d, const uint32_t* a, const uint32_t* b) {
    asm volatile(
        "mma.sync.aligned.m16n8k8.row.col.f32.tf32.tf32.f32 "
        "{%0,%1,%2,%3}, {%4,%5,%6,%7}, {%8,%9}, {%0,%1,%2,%3};\n"
        : "+f"(d[0]), "+f"(d[1]), "+f"(d[2]), "+f"(d[3])
        : "r"(a[0]), "r"(a[1]), "r"(a[2]), "r"(a[3]), "r"(b[0]), "r"(b[1]));
}

__device__ __forceinline__ void mma3(float* d, const uint32_t* ah, const uint32_t* al,
                                     const uint32_t* bh, const uint32_t* bl) {
    mma_tf32(d, ah, bh);
    mma_tf32(d, al, bh);
    mma_tf32(d, ah, bl);
}

__device__ __forceinline__ void cp16(void* s, const void* g) {
    uint32_t sa = (uint32_t)__cvta_generic_to_shared(s);
    asm volatile("cp.async.cg.shared.global [%0], [%1], 16;" :: "r"(sa), "l"(g));
}
#define CP_COMMIT() asm volatile("cp.async.commit_group;")
template <int N> __device__ __forceinline__ void cp_wait() {
    asm volatile("cp.async.wait_group %0;" :: "n"(N));
}

// ---------------------------------------------------------------------------
// GEMM1: E_partial[ks] = V_chunk * V_chunk^T, exploiting symmetry.
// grid.y = 3: tile 0 = (0,0), tile 1 = (128,128), tile 2 = (0,128) + mirror.
// 2-stage cp.async pipeline. Mask-split 3xTF32.
// ---------------------------------------------------------------------------
__global__ __launch_bounds__(256) void gemm1_kernel(const float* __restrict__ x) {
    const int ks   = blockIdx.x;
    const int tile = blockIdx.y;           // 0..2
    const int b    = blockIdx.z;
    const int tm = (tile == 1) ? 128 : 0;
    const int tn = (tile == 0) ? 0 : 128;
    const bool diag = (tile < 2);
    const float* __restrict__ V = x + (size_t)b * CDIM * SDIM;
    const int k0 = ks * KC;

    extern __shared__ float smem[];
    const int TILE = 128 * 36;

    const int tid  = threadIdx.x;
    const int lane = tid & 31;
    const int wid  = tid >> 5;
    const int gid  = lane >> 2;
    const int tig  = lane & 3;
    const int warpM = wid >> 2;            // 0..1
    const int warpN = wid & 3;             // 0..3

    float acc[4][4][4];
    #pragma unroll
    for (int i = 0; i < 4; i++)
        #pragma unroll
        for (int j = 0; j < 4; j++)
            #pragma unroll
            for (int k = 0; k < 4; k++) acc[i][j][k] = 0.f;

    const int ldRow = tid >> 3;            // 0..31
    const int ldCol = (tid & 7) * 4;       // 0..28

    auto issue = [&](int buf, int kb) {
        float* A = smem + buf * 2 * TILE;
        float* B = A + TILE;
        #pragma unroll
        for (int p = 0; p < 4; p++) {
            const int row = p * 32 + ldRow;
            cp16(A + row * 36 + ldCol, V + (size_t)(tm + row) * SDIM + k0 + kb + ldCol);
            if (!diag)
                cp16(B + row * 36 + ldCol, V + (size_t)(tn + row) * SDIM + k0 + kb + ldCol);
        }
        CP_COMMIT();
    };

    issue(0, 0);
    int buf = 0;

    for (int kb = 0; kb < KC; kb += BK) {
        const bool more = (kb + BK < KC);
        if (more) issue(buf ^ 1, kb + BK);
        if (more) cp_wait<1>(); else cp_wait<0>();
        __syncthreads();

        float* A = smem + buf * 2 * TILE;
        float* B = diag ? A : (A + TILE);

        #pragma unroll
        for (int kk = 0; kk < BK; kk += 8) {
            uint32_t ah[4][4], al[4][4], bh[4][2], bl[4][2];
            #pragma unroll
            for (int mr = 0; mr < 4; mr++) {
                const int r0 = warpM * 64 + mr * 16;
                split_mask(A[(r0 + gid    ) * 36 + kk + tig    ], ah[mr][0], al[mr][0]);
                split_mask(A[(r0 + 8 + gid) * 36 + kk + tig    ], ah[mr][1], al[mr][1]);
                split_mask(A[(r0 + gid    ) * 36 + kk + tig + 4], ah[mr][2], al[mr][2]);
                split_mask(A[(r0 + 8 + gid) * 36 + kk + tig + 4], ah[mr][3], al[mr][3]);
            }
            #pragma unroll
            for (int nc = 0; nc < 4; nc++) {
                const int n0 = warpN * 32 + nc * 8;
                split_mask(B[(n0 + gid) * 36 + kk + tig    ], bh[nc][0], bl[nc][0]);
                split_mask(B[(n0 + gid) * 36 + kk + tig + 4], bh[nc][1], bl[nc][1]);
            }
            #pragma unroll
            for (int mr = 0; mr < 4; mr++)
                #pragma unroll
                for (int nc = 0; nc < 4; nc++)
                    mma3(acc[mr][nc], ah[mr], al[mr], bh[nc], bl[nc]);
        }
        __syncthreads();
        buf ^= 1;
    }

    float* Ep = &g_Ep[ks][(size_t)b * CDIM * CDIM];
    #pragma unroll
    for (int mr = 0; mr < 4; mr++) {
        const int r = tm + warpM * 64 + mr * 16 + gid;
        #pragma unroll
        for (int nc = 0; nc < 4; nc++) {
            const int c = tn + warpN * 32 + nc * 8 + tig * 2;
            *(float2*)&Ep[(size_t)r * CDIM + c]       = make_float2(acc[mr][nc][0], acc[mr][nc][1]);
            *(float2*)&Ep[(size_t)(r + 8) * CDIM + c] = make_float2(acc[mr][nc][2], acc[mr][nc][3]);
            if (!diag) {  // mirror into the (128,0) quadrant
                Ep[(size_t)c * CDIM + r]           = acc[mr][nc][0];
                Ep[(size_t)(c + 1) * CDIM + r]     = acc[mr][nc][1];
                Ep[(size_t)c * CDIM + r + 8]       = acc[mr][nc][2];
                Ep[(size_t)(c + 1) * CDIM + r + 8] = acc[mr][nc][3];
            }
        }
    }
}

// ---------------------------------------------------------------------------
// Softmax: reduce split-K partials, w[row,:] = softmax(-E[row,:]).
// ---------------------------------------------------------------------------
__global__ __launch_bounds__(256) void softmax_kernel() {
    const int row = blockIdx.x;
    const int tid = threadIdx.x;
    const int lane = tid & 31;
    const int wid  = tid >> 5;

    float e = 0.f;
    #pragma unroll
    for (int ks = 0; ks < KSPLIT; ks++)
        e += g_Ep[ks][(size_t)row * CDIM + tid];

    __shared__ float red[8];

    float m = e;
    #pragma unroll
    for (int o = 16; o > 0; o >>= 1) m = fminf(m, __shfl_xor_sync(0xffffffffu, m, o));
    if (lane == 0) red[wid] = m;
    __syncthreads();
    float mn = red[0];
    #pragma unroll
    for (int i = 1; i < 8; i++) mn = fminf(mn, red[i]);
    __syncthreads();

    const float ex = expf(mn - e);

    float s = ex;
    #pragma unroll
    for (int o = 16; o > 0; o >>= 1) s += __shfl_xor_sync(0xffffffffu, s, o);
    if (lane == 0) red[wid] = s;
    __syncthreads();
    float st = red[0];
    #pragma unroll
    for (int i = 1; i < 8; i++) st += red[i];

    g_W[(size_t)row * CDIM + tid] = ex / st;
}

// ---------------------------------------------------------------------------
// GEMM2: out = alpha * (W @ V) + x.  2-stage cp.async pipeline. Mask-split 3xTF32.
// ---------------------------------------------------------------------------
__global__ __launch_bounds__(256) void gemm2_kernel(const float* __restrict__ x,
                                                    const float* __restrict__ alpha,
                                                    float* __restrict__ out) {
    const int sTile = blockIdx.x;
    const int mTile = blockIdx.y;
    const int b     = blockIdx.z;
    const int s0 = sTile * 128;
    const int m0 = mTile * 128;
    const float* __restrict__ V  = x + (size_t)b * CDIM * SDIM;
    const float* __restrict__ Wm = g_W + (size_t)b * CDIM * CDIM;

    extern __shared__ float smem[];
    const int ATILE = 128 * 36;
    const int BTILE = 32 * 136;
    const int STAGE = ATILE + BTILE;

    const int tid  = threadIdx.x;
    const int lane = tid & 31;
    const int wid  = tid >> 5;
    const int gid  = lane >> 2;
    const int tig  = lane & 3;
    const int warpM = wid >> 2;
    const int warpN = wid & 3;

    float acc[4][4][4];
    #pragma unroll
    for (int i = 0; i < 4; i++)
        #pragma unroll
        for (int j = 0; j < 4; j++)
            #pragma unroll
            for (int k = 0; k < 4; k++) acc[i][j][k] = 0.f;

    const int aRow = tid >> 3;
    const int aCol = (tid & 7) * 4;
    const int bRowBase = tid >> 5;
    const int bCol = (tid & 31) * 4;

    auto issue = [&](int buf, int kb) {
        float* A = smem + buf * STAGE;
        float* B = A + ATILE;
        #pragma unroll
        for (int p = 0; p < 4; p++) {
            const int row = p * 32 + aRow;
            cp16(A + row * 36 + aCol, Wm + (size_t)(m0 + row) * CDIM + kb + aCol);
        }
        #pragma unroll
        for (int p = 0; p < 4; p++) {
            const int kr = p * 8 + bRowBase;
            cp16(B + kr * 136 + bCol, V + (size_t)(kb + kr) * SDIM + s0 + bCol);
        }
        CP_COMMIT();
    };

    issue(0, 0);
    int buf = 0;

    for (int kb = 0; kb < CDIM; kb += BK) {
        const bool more = (kb + BK < CDIM);
        if (more) issue(buf ^ 1, kb + BK);
        if (more) cp_wait<1>(); else cp_wait<0>();
        __syncthreads();

        float* A = smem + buf * STAGE;
        float* B = A + ATILE;

        #pragma unroll
        for (int kk = 0; kk < BK; kk += 8) {
            uint32_t ah[4][4], al[4][4], bh[4][2], bl[4][2];
            #pragma unroll
            for (int mr = 0; mr < 4; mr++) {
                const int r0 = warpM * 64 + mr * 16;
                split_mask(A[(r0 + gid    ) * 36 + kk + tig    ], ah[mr][0], al[mr][0]);
                split_mask(A[(r0 + 8 + gid) * 36 + kk + tig    ], ah[mr][1], al[mr][1]);
                split_mask(A[(r0 + gid    ) * 36 + kk + tig + 4], ah[mr][2], al[mr][2]);
                split_mask(A[(r0 + 8 + gid) * 36 + kk + tig + 4], ah[mr][3], al[mr][3]);
            }
            #pragma unroll
            for (int nc = 0; nc < 4; nc++) {
                const int n0 = warpN * 32 + nc * 8;
                split_mask(B[(kk + tig    ) * 136 + n0 + gid], bh[nc][0], bl[nc][0]);
                split_mask(B[(kk + tig + 4) * 136 + n0 + gid], bh[nc][1], bl[nc][1]);
            }
            #pragma unroll
            for (int mr = 0; mr < 4; mr++)
                #pragma unroll
                for (int nc = 0; nc < 4; nc++)
                    mma3(acc[mr][nc], ah[mr], al[mr], bh[nc], bl[nc]);
        }
        __syncthreads();
        buf ^= 1;
    }

    const float av = *alpha;
    float* outB = out + (size_t)b * CDIM * SDIM;
    #pragma unroll
    for (int mr = 0; mr < 4; mr++) {
        const int r = m0 + warpM * 64 + mr * 16 + gid;
        #pragma unroll
        for (int nc = 0; nc < 4; nc++) {
            const int s = s0 + warpN * 32 + nc * 8 + tig * 2;
            const size_t i0 = (size_t)r * SDIM + s;
            const size_t i1 = i0 + (size_t)8 * SDIM;
            const float2 x0 = *(const float2*)(V + i0);
            const float2 x1 = *(const float2*)(V + i1);
            *(float2*)(outB + i0) = make_float2(fmaf(av, acc[mr][nc][0], x0.x),
                                                fmaf(av, acc[mr][nc][1], x0.y));
            *(float2*)(outB + i1) = make_float2(fmaf(av, acc[mr][nc][2], x1.x),
                                                fmaf(av, acc[mr][nc][3], x1.y));
        }
    }
}

extern "C" void kernel_launch(void* const* d_in, const int* in_sizes, int n_in,
                              void* d_out, int out_size) {
    const float* x     = (const float*)d_in[0];
    const float* alpha = (const float*)d_in[1];
    float* out = (float*)d_out;

    const int smem1 = 4 * 128 * 36 * 4;                    // 73728 B
    const int smem2 = 2 * (128 * 36 + 32 * 136) * 4;       // 71680 B
    cudaFuncSetAttribute(gemm1_kernel, cudaFuncAttributeMaxDynamicSharedMemorySize, smem1);
    cudaFuncSetAttribute(gemm2_kernel, cudaFuncAttributeMaxDynamicSharedMemorySize, smem2);

    gemm1_kernel<<<dim3(KSPLIT, 3, BDIM), 256, smem1>>>(x);
    softmax_kernel<<<BDIM * CDIM, 256>>>();
    gemm2_kernel<<<dim3(SDIM / 128, 2, BDIM), 256, smem2>>>(x, alpha, out);
}

// round 6
// speedup vs baseline: 1.8151x; 1.0282x over previous
#include <cuda_runtime.h>
#include <cstdint>

#define BDIM 8
#define CDIM 256
#define SDIM 16384
#define KSPLIT 24
#define BK 32
#define NBLK (SDIM / BK)        // 512 BK-blocks total
#define BASE_BLK (NBLK / KSPLIT)       // 21
#define REM_BLK  (NBLK - BASE_BLK * KSPLIT)  // 8  (chunks 0..7 get +1)

// Scratch (static device memory — allowed; no runtime allocation).
__device__ float g_Ep[KSPLIT][BDIM * CDIM * CDIM];  // split-K partials of E
__device__ float g_W[BDIM * CDIM * CDIM];           // softmax weights

// Mask-based 3xTF32 split: hi = raw fp32 (tensor core truncates to tf32),
// lo = v - trunc_tf32(v).  No cvt instructions.
__device__ __forceinline__ void split_mask(float v, uint32_t& hi, uint32_t& lo) {
    const uint32_t u = __float_as_uint(v);
    hi = u;
    lo = __float_as_uint(v - __uint_as_float(u & 0xFFFFE000u));
}

__device__ __forceinline__ void mma_tf32(float* d, const uint32_t* a, const uint32_t* b) {
    asm volatile(
        "mma.sync.aligned.m16n8k8.row.col.f32.tf32.tf32.f32 "
        "{%0,%1,%2,%3}, {%4,%5,%6,%7}, {%8,%9}, {%0,%1,%2,%3};\n"
        : "+f"(d[0]), "+f"(d[1]), "+f"(d[2]), "+f"(d[3])
        : "r"(a[0]), "r"(a[1]), "r"(a[2]), "r"(a[3]), "r"(b[0]), "r"(b[1]));
}

__device__ __forceinline__ void mma3(float* d, const uint32_t* ah, const uint32_t* al,
                                     const uint32_t* bh, const uint32_t* bl) {
    mma_tf32(d, ah, bh);
    mma_tf32(d, al, bh);
    mma_tf32(d, ah, bl);
}

__device__ __forceinline__ void cp16(void* s, const void* g) {
    uint32_t sa = (uint32_t)__cvta_generic_to_shared(s);
    asm volatile("cp.async.cg.shared.global [%0], [%1], 16;" :: "r"(sa), "l"(g));
}
#define CP_COMMIT() asm volatile("cp.async.commit_group;")
template <int N> __device__ __forceinline__ void cp_wait() {
    asm volatile("cp.async.wait_group %0;" :: "n"(N));
}

// ---------------------------------------------------------------------------
// GEMM1: E_partial[ks] = V_chunk * V_chunk^T, exploiting symmetry.
// grid: (KSPLIT=24, 3 tiles, 8 batches) = 576 CTAs = 2 nearly-full waves.
// Non-uniform K-chunks (22 or 21 BK-blocks). 2-stage cp.async. Mask 3xTF32.
// ---------------------------------------------------------------------------
__global__ __launch_bounds__(256) void gemm1_kernel(const float* __restrict__ x) {
    const int ks   = blockIdx.x;           // 0..KSPLIT-1
    const int tile = blockIdx.y;           // 0..2
    const int b    = blockIdx.z;
    const int tm = (tile == 1) ? 128 : 0;
    const int tn = (tile == 0) ? 0 : 128;
    const bool diag = (tile < 2);
    const float* __restrict__ V = x + (size_t)b * CDIM * SDIM;

    // chunk [kb0, kb1) in elements
    const int blk0 = ks * BASE_BLK + (ks < REM_BLK ? ks : REM_BLK);
    const int nblk = BASE_BLK + (ks < REM_BLK ? 1 : 0);
    const int kb0  = blk0 * BK;
    const int kb1  = kb0 + nblk * BK;

    extern __shared__ float smem[];
    const int TILE = 128 * 36;

    const int tid  = threadIdx.x;
    const int lane = tid & 31;
    const int wid  = tid >> 5;
    const int gid  = lane >> 2;
    const int tig  = lane & 3;
    const int warpM = wid >> 2;            // 0..1
    const int warpN = wid & 3;             // 0..3

    float acc[4][4][4];
    #pragma unroll
    for (int i = 0; i < 4; i++)
        #pragma unroll
        for (int j = 0; j < 4; j++)
            #pragma unroll
            for (int k = 0; k < 4; k++) acc[i][j][k] = 0.f;

    const int ldRow = tid >> 3;            // 0..31
    const int ldCol = (tid & 7) * 4;       // 0..28

    auto issue = [&](int buf, int kb) {
        float* A = smem + buf * 2 * TILE;
        float* B = A + TILE;
        #pragma unroll
        for (int p = 0; p < 4; p++) {
            const int row = p * 32 + ldRow;
            cp16(A + row * 36 + ldCol, V + (size_t)(tm + row) * SDIM + kb + ldCol);
            if (!diag)
                cp16(B + row * 36 + ldCol, V + (size_t)(tn + row) * SDIM + kb + ldCol);
        }
        CP_COMMIT();
    };

    issue(0, kb0);
    int buf = 0;

    for (int kb = kb0; kb < kb1; kb += BK) {
        const bool more = (kb + BK < kb1);
        if (more) issue(buf ^ 1, kb + BK);
        if (more) cp_wait<1>(); else cp_wait<0>();
        __syncthreads();

        float* A = smem + buf * 2 * TILE;
        float* B = diag ? A : (A + TILE);

        #pragma unroll
        for (int kk = 0; kk < BK; kk += 8) {
            uint32_t ah[4][4], al[4][4], bh[4][2], bl[4][2];
            #pragma unroll
            for (int mr = 0; mr < 4; mr++) {
                const int r0 = warpM * 64 + mr * 16;
                split_mask(A[(r0 + gid    ) * 36 + kk + tig    ], ah[mr][0], al[mr][0]);
                split_mask(A[(r0 + 8 + gid) * 36 + kk + tig    ], ah[mr][1], al[mr][1]);
                split_mask(A[(r0 + gid    ) * 36 + kk + tig + 4], ah[mr][2], al[mr][2]);
                split_mask(A[(r0 + 8 + gid) * 36 + kk + tig + 4], ah[mr][3], al[mr][3]);
            }
            #pragma unroll
            for (int nc = 0; nc < 4; nc++) {
                const int n0 = warpN * 32 + nc * 8;
                split_mask(B[(n0 + gid) * 36 + kk + tig    ], bh[nc][0], bl[nc][0]);
                split_mask(B[(n0 + gid) * 36 + kk + tig + 4], bh[nc][1], bl[nc][1]);
            }
            #pragma unroll
            for (int mr = 0; mr < 4; mr++)
                #pragma unroll
                for (int nc = 0; nc < 4; nc++)
                    mma3(acc[mr][nc], ah[mr], al[mr], bh[nc], bl[nc]);
        }
        __syncthreads();
        buf ^= 1;
    }

    float* Ep = &g_Ep[ks][(size_t)b * CDIM * CDIM];
    #pragma unroll
    for (int mr = 0; mr < 4; mr++) {
        const int r = tm + warpM * 64 + mr * 16 + gid;
        #pragma unroll
        for (int nc = 0; nc < 4; nc++) {
            const int c = tn + warpN * 32 + nc * 8 + tig * 2;
            *(float2*)&Ep[(size_t)r * CDIM + c]       = make_float2(acc[mr][nc][0], acc[mr][nc][1]);
            *(float2*)&Ep[(size_t)(r + 8) * CDIM + c] = make_float2(acc[mr][nc][2], acc[mr][nc][3]);
            if (!diag) {  // mirror into the (128,0) quadrant
                Ep[(size_t)c * CDIM + r]           = acc[mr][nc][0];
                Ep[(size_t)(c + 1) * CDIM + r]     = acc[mr][nc][1];
                Ep[(size_t)c * CDIM + r + 8]       = acc[mr][nc][2];
                Ep[(size_t)(c + 1) * CDIM + r + 8] = acc[mr][nc][3];
            }
        }
    }
}

// ---------------------------------------------------------------------------
// Softmax: reduce split-K partials, w[row,:] = softmax(-E[row,:]).
// ---------------------------------------------------------------------------
__global__ __launch_bounds__(256) void softmax_kernel() {
    const int row = blockIdx.x;
    const int tid = threadIdx.x;
    const int lane = tid & 31;
    const int wid  = tid >> 5;

    float e = 0.f;
    #pragma unroll
    for (int ks = 0; ks < KSPLIT; ks++)
        e += g_Ep[ks][(size_t)row * CDIM + tid];

    __shared__ float red[8];

    float m = e;
    #pragma unroll
    for (int o = 16; o > 0; o >>= 1) m = fminf(m, __shfl_xor_sync(0xffffffffu, m, o));
    if (lane == 0) red[wid] = m;
    __syncthreads();
    float mn = red[0];
    #pragma unroll
    for (int i = 1; i < 8; i++) mn = fminf(mn, red[i]);
    __syncthreads();

    const float ex = expf(mn - e);

    float s = ex;
    #pragma unroll
    for (int o = 16; o > 0; o >>= 1) s += __shfl_xor_sync(0xffffffffu, s, o);
    if (lane == 0) red[wid] = s;
    __syncthreads();
    float st = red[0];
    #pragma unroll
    for (int i = 1; i < 8; i++) st += red[i];

    g_W[(size_t)row * CDIM + tid] = ex / st;
}

// ---------------------------------------------------------------------------
// GEMM2: out = alpha * (W @ V) + x.  2-stage cp.async pipeline. Mask 3xTF32.
// ---------------------------------------------------------------------------
__global__ __launch_bounds__(256) void gemm2_kernel(const float* __restrict__ x,
                                                    const float* __restrict__ alpha,
                                                    float* __restrict__ out) {
    const int sTile = blockIdx.x;
    const int mTile = blockIdx.y;
    const int b     = blockIdx.z;
    const int s0 = sTile * 128;
    const int m0 = mTile * 128;
    const float* __restrict__ V  = x + (size_t)b * CDIM * SDIM;
    const float* __restrict__ Wm = g_W + (size_t)b * CDIM * CDIM;

    extern __shared__ float smem[];
    const int ATILE = 128 * 36;
    const int BTILE = 32 * 136;
    const int STAGE = ATILE + BTILE;

    const int tid  = threadIdx.x;
    const int lane = tid & 31;
    const int wid  = tid >> 5;
    const int gid  = lane >> 2;
    const int tig  = lane & 3;
    const int warpM = wid >> 2;
    const int warpN = wid & 3;

    float acc[4][4][4];
    #pragma unroll
    for (int i = 0; i < 4; i++)
        #pragma unroll
        for (int j = 0; j < 4; j++)
            #pragma unroll
            for (int k = 0; k < 4; k++) acc[i][j][k] = 0.f;

    const int aRow = tid >> 3;
    const int aCol = (tid & 7) * 4;
    const int bRowBase = tid >> 5;
    const int bCol = (tid & 31) * 4;

    auto issue = [&](int buf, int kb) {
        float* A = smem + buf * STAGE;
        float* B = A + ATILE;
        #pragma unroll
        for (int p = 0; p < 4; p++) {
            const int row = p * 32 + aRow;
            cp16(A + row * 36 + aCol, Wm + (size_t)(m0 + row) * CDIM + kb + aCol);
        }
        #pragma unroll
        for (int p = 0; p < 4; p++) {
            const int kr = p * 8 + bRowBase;
            cp16(B + kr * 136 + bCol, V + (size_t)(kb + kr) * SDIM + s0 + bCol);
        }
        CP_COMMIT();
    };

    issue(0, 0);
    int buf = 0;

    for (int kb = 0; kb < CDIM; kb += BK) {
        const bool more = (kb + BK < CDIM);
        if (more) issue(buf ^ 1, kb + BK);
        if (more) cp_wait<1>(); else cp_wait<0>();
        __syncthreads();

        float* A = smem + buf * STAGE;
        float* B = A + ATILE;

        #pragma unroll
        for (int kk = 0; kk < BK; kk += 8) {
            uint32_t ah[4][4], al[4][4], bh[4][2], bl[4][2];
            #pragma unroll
            for (int mr = 0; mr < 4; mr++) {
                const int r0 = warpM * 64 + mr * 16;
                split_mask(A[(r0 + gid    ) * 36 + kk + tig    ], ah[mr][0], al[mr][0]);
                split_mask(A[(r0 + 8 + gid) * 36 + kk + tig    ], ah[mr][1], al[mr][1]);
                split_mask(A[(r0 + gid    ) * 36 + kk + tig + 4], ah[mr][2], al[mr][2]);
                split_mask(A[(r0 + 8 + gid) * 36 + kk + tig + 4], ah[mr][3], al[mr][3]);
            }
            #pragma unroll
            for (int nc = 0; nc < 4; nc++) {
                const int n0 = warpN * 32 + nc * 8;
                split_mask(B[(kk + tig    ) * 136 + n0 + gid], bh[nc][0], bl[nc][0]);
                split_mask(B[(kk + tig + 4) * 136 + n0 + gid], bh[nc][1], bl[nc][1]);
            }
            #pragma unroll
            for (int mr = 0; mr < 4; mr++)
                #pragma unroll
                for (int nc = 0; nc < 4; nc++)
                    mma3(acc[mr][nc], ah[mr], al[mr], bh[nc], bl[nc]);
        }
        __syncthreads();
        buf ^= 1;
    }

    const float av = *alpha;
    float* outB = out + (size_t)b * CDIM * SDIM;
    #pragma unroll
    for (int mr = 0; mr < 4; mr++) {
        const int r = m0 + warpM * 64 + mr * 16 + gid;
        #pragma unroll
        for (int nc = 0; nc < 4; nc++) {
            const int s = s0 + warpN * 32 + nc * 8 + tig * 2;
            const size_t i0 = (size_t)r * SDIM + s;
            const size_t i1 = i0 + (size_t)8 * SDIM;
            const float2 x0 = *(const float2*)(V + i0);
            const float2 x1 = *(const float2*)(V + i1);
            *(float2*)(outB + i0) = make_float2(fmaf(av, acc[mr][nc][0], x0.x),
                                                fmaf(av, acc[mr][nc][1], x0.y));
            *(float2*)(outB + i1) = make_float2(fmaf(av, acc[mr][nc][2], x1.x),
                                                fmaf(av, acc[mr][nc][3], x1.y));
        }
    }
}

extern "C" void kernel_launch(void* const* d_in, const int* in_sizes, int n_in,
                              void* d_out, int out_size) {
    const float* x     = (const float*)d_in[0];
    const float* alpha = (const float*)d_in[1];
    float* out = (float*)d_out;

    const int smem1 = 4 * 128 * 36 * 4;                    // 73728 B
    const int smem2 = 2 * (128 * 36 + 32 * 136) * 4;       // 71680 B
    cudaFuncSetAttribute(gemm1_kernel, cudaFuncAttributeMaxDynamicSharedMemorySize, smem1);
    cudaFuncSetAttribute(gemm2_kernel, cudaFuncAttributeMaxDynamicSharedMemorySize, smem2);

    gemm1_kernel<<<dim3(KSPLIT, 3, BDIM), 256, smem1>>>(x);
    softmax_kernel<<<BDIM * CDIM, 256>>>();
    gemm2_kernel<<<dim3(SDIM / 128, 2, BDIM), 256, smem2>>>(x, alpha, out);
}